// round 1
// baseline (speedup 1.0000x reference)
#include <cuda_runtime.h>

// Problem: nonlinear scalar RNN scan over B*T = 1,048,576 sequential steps.
// Strategy: chunked fixed-point iteration exploiting contraction (|Jacobian| <~ 0.75).
//   - 4096 chunks x 256 steps (row-aligned: 16 rows of T=16 per chunk)
//   - K=4 relaxation sweeps propagate/converge chunk-boundary states
//   - final pass replays chunks and writes the 6 outputs at each row's last step
// All launches are plain kernel launches on the default stream (graph-capturable),
// scratch lives in __device__ globals (no allocation).

#define TT 16
#define CHUNK 256
#define MAXCHUNK 8192

__device__ float g_bufA[MAXCHUNK + 1];
__device__ float g_bufB[MAXCHUNK + 1];

struct SP {
  float A1, B1, oo1;    // sigmoid path: exp(-z1) = ex2(A1*c + B1), oo = oo1 * sigmoid
  float A2, B2;         // tanh path:    exp(2*z2) = ex2(A2*c + B2)
  float sv, m2sv;       // ov1 = sv*tanh = fma(m2sv, rcp(1+e2), sv)
  float E;              // eb * 500
};

__device__ __forceinline__ float ex2f(float x) {
  float y; asm("ex2.approx.f32 %0, %1;" : "=f"(y) : "f"(x)); return y;
}
__device__ __forceinline__ float rcpf(float x) {
  float y; asm("rcp.approx.f32 %0, %1;" : "=f"(y) : "f"(x)); return y;
}

__device__ __forceinline__ SP make_params(
    const float* cm, const float* cs,
    const float* wr_om, const float* wr_fm, const float* wr_vm,
    const float* b0_om, const float* wb1_om, const float* ws_vm, const float* b0_rm) {
  const float L2E = 1.4426950408889634f;
  float mo = cm[0], so = cs[0];
  float e_om = expf(wr_om[0]);
  float e_fm = expf(wr_fm[0]);
  float oo1 = e_om / (e_om + e_fm);
  float wb1 = wb1_om[0], b0 = b0_om[0];
  float eb = expf(b0_rm[0]);
  float ws = expf(ws_vm[0]);
  float sv = 1.0f / (1.0f + expf(-wr_vm[0]));
  float k1 = wb1 / so;
  SP p;
  p.A1 = -L2E * k1;                    // exp(-z1), z1 = b0 + (c-mo)*k1
  p.B1 = -L2E * (b0 - mo * k1);
  p.oo1 = oo1;
  p.A2 = 2.0f * L2E * ws * (1.0f / 500.0f);   // exp(2*z2), z2 = (c/500 - eb)*ws
  p.B2 = -2.0f * L2E * eb * ws;
  p.sv = sv;
  p.m2sv = -2.0f * sv;
  p.E = 500.0f * eb;
  return p;
}

// One recurrence step (no outputs). Critical path ~52-56 cycles.
__device__ __forceinline__ float step_c(float c, float u, const SP& P) {
  float e1 = ex2f(fmaf(c, P.A1, P.B1));
  float r1 = rcpf(1.0f + e1);
  float f  = fmaf(-P.oo1, r1, 1.0f);           // f = 1 - oo1*sigmoid(z1)
  float e2 = ex2f(fmaf(c, P.A2, P.B2));
  float r2 = rcpf(1.0f + e2);
  float ov1 = fmaf(P.m2sv, r2, P.sv);          // sv * tanh(z2)
  float ov = fminf(ov1, f);                    // ov1 - relu(ov1 - f)
  float a  = fabsf(c - P.E);
  float fcu = fmaf(f, c, u);
  return fmaf(-ov, a, fcu);                    // f*c + u + mr,  mr = -ov*|c-E|
}

// init: fill start-state guesses with Ini_C; zero output rows b < time_lag
__global__ void init_kernel(const float* IniC, float* out, const int* tlp, int Bn) {
  int i = blockIdx.x * blockDim.x + threadIdx.x;
  float c0 = IniC[0];
  if (i <= MAXCHUNK) g_bufA[i] = c0;
  int tl = tlp[0];
  if (i < tl && i < Bn) {
    #pragma unroll
    for (int j = 0; j < 6; j++) out[(long)j * Bn + i] = 0.0f;
  }
}

// one relaxation sweep: read start states, run chunk, write end state to next slot
__global__ void iter_kernel(
    const float* __restrict__ x,
    const float* cm, const float* cs,
    const float* wr_om, const float* wr_fm, const float* wr_vm,
    const float* b0_om, const float* wb1_om, const float* ws_vm, const float* b0_rm,
    const float* IniC, const int* tlp, int BT, int dir) {
  int p = blockIdx.x * blockDim.x + threadIdx.x;
  const float* s_in = dir ? g_bufB : g_bufA;
  float* s_out = dir ? g_bufA : g_bufB;
  int tl = tlp[0];
  int nsteps = BT - tl * TT;
  int nchunk = (nsteps + CHUNK - 1) / CHUNK;
  if (p == 0) s_out[0] = IniC[0];
  if (p >= nchunk || p >= MAXCHUNK) return;
  SP P = make_params(cm, cs, wr_om, wr_fm, wr_vm, b0_om, wb1_om, ws_vm, b0_rm);
  float c = s_in[p];
  const float* xp = x + tl * TT + p * CHUNK;
  int m = min(CHUNK, nsteps - p * CHUNK);
  #pragma unroll 16
  for (int i = 0; i < m; i++) {
    c = step_c(c, xp[i], P);
  }
  s_out[p + 1] = c;
}

// final pass: replay each chunk from converged start state, emitting outputs at
// the last step of each row (global step index ≡ 15 mod 16).
__global__ void out_kernel(
    const float* __restrict__ x,
    const float* cm, const float* cs,
    const float* wr_om, const float* wr_fm, const float* wr_vm,
    const float* b0_om, const float* wb1_om, const float* ws_vm, const float* b0_rm,
    const int* tlp, int BT, int Bn, float* __restrict__ out) {
  int p = blockIdx.x * blockDim.x + threadIdx.x;
  int tl = tlp[0];
  int nsteps = BT - tl * TT;
  int nchunk = (nsteps + CHUNK - 1) / CHUNK;
  if (p >= nchunk || p >= MAXCHUNK) return;
  SP P = make_params(cm, cs, wr_om, wr_fm, wr_vm, b0_om, wb1_om, ws_vm, b0_rm);
  float c = g_bufA[p];   // final converged buffer (after even # of sweeps)
  const float* xp = x + tl * TT + p * CHUNK;
  int m = min(CHUNK, nsteps - p * CHUNK);

  float* h_n  = out;
  float* c_n  = out + (long)Bn;
  float* oo_o = out + 2L * Bn;
  float* f_o  = out + 3L * Bn;
  float* ov_o = out + 4L * Bn;
  float* mr_o = out + 5L * Bn;

  #pragma unroll 16
  for (int i = 0; i < m; i++) {
    float u = xp[i];
    float e1 = ex2f(fmaf(c, P.A1, P.B1));
    float r1 = rcpf(1.0f + e1);
    float f  = fmaf(-P.oo1, r1, 1.0f);
    float e2 = ex2f(fmaf(c, P.A2, P.B2));
    float r2 = rcpf(1.0f + e2);
    float ov1 = fmaf(P.m2sv, r2, P.sv);
    float ov = fminf(ov1, f);
    float a  = fabsf(c - P.E);
    float fcu = fmaf(f, c, u);
    if ((i & (TT - 1)) == (TT - 1)) {
      int row = tl + ((p * CHUNK + i) >> 4);
      float oo = P.oo1 * r1;
      h_n[row]  = oo * c;       // oo * c_old
      c_n[row]  = c;            // c_old
      oo_o[row] = oo;
      f_o[row]  = f;
      ov_o[row] = ov;
      mr_o[row] = -ov * a;
    }
    c = fmaf(-ov, a, fcu);
  }
}

extern "C" void kernel_launch(void* const* d_in, const int* in_sizes, int n_in,
                              void* d_out, int out_size) {
  const float* x      = (const float*)d_in[0];
  // d_in[1] y_obs: unused
  const float* cm     = (const float*)d_in[2];
  const float* cs     = (const float*)d_in[3];
  const float* IniC   = (const float*)d_in[4];
  const float* wr_om  = (const float*)d_in[5];
  const float* wr_fm  = (const float*)d_in[6];
  const float* wr_vm  = (const float*)d_in[7];
  const float* b0_om  = (const float*)d_in[8];
  const float* wb1_om = (const float*)d_in[9];
  const float* ws_vm  = (const float*)d_in[10];
  const float* b0_rm  = (const float*)d_in[11];
  // d_in[12] epoch: unused
  const int*   tlp    = (const int*)d_in[13];
  float* out = (float*)d_out;

  int BT = in_sizes[0];
  int Bn = out_size / 6;

  int nchunk_max = (BT + CHUNK - 1) / CHUNK;
  if (nchunk_max > MAXCHUNK) nchunk_max = MAXCHUNK;

  const int TPB = 256;
  int init_n = (Bn > MAXCHUNK + 1) ? Bn : (MAXCHUNK + 1);
  init_kernel<<<(init_n + TPB - 1) / TPB, TPB>>>(IniC, out, tlp, Bn);

  int gb = (nchunk_max + TPB - 1) / TPB;
  // K = 4 relaxation sweeps (A->B->A->B->A), final state lands in bufA
  iter_kernel<<<gb, TPB>>>(x, cm, cs, wr_om, wr_fm, wr_vm, b0_om, wb1_om, ws_vm, b0_rm, IniC, tlp, BT, 0);
  iter_kernel<<<gb, TPB>>>(x, cm, cs, wr_om, wr_fm, wr_vm, b0_om, wb1_om, ws_vm, b0_rm, IniC, tlp, BT, 1);
  iter_kernel<<<gb, TPB>>>(x, cm, cs, wr_om, wr_fm, wr_vm, b0_om, wb1_om, ws_vm, b0_rm, IniC, tlp, BT, 0);
  iter_kernel<<<gb, TPB>>>(x, cm, cs, wr_om, wr_fm, wr_vm, b0_om, wb1_om, ws_vm, b0_rm, IniC, tlp, BT, 1);

  out_kernel<<<gb, TPB>>>(x, cm, cs, wr_om, wr_fm, wr_vm, b0_om, wb1_om, ws_vm, b0_rm, tlp, BT, Bn, out);
}

// round 3
// speedup vs baseline: 3.9206x; 3.9206x over previous
#include <cuda_runtime.h>

// Nonlinear scalar RNN scan, B*T = 1,048,576 sequential steps.
// Chunked fixed-point relaxation (strong contraction, |J_eff| well below 1):
//   CHUNK=128 steps (8 rows of T=16), nchunk = 8192
//   sweep1 (guess=Ini_C) -> sweep -> sweep -> out  (4 passes total)
// Per-step dependent chain ~52 cyc (2x MUFU paths in parallel); x loads are
// float4 + software prefetch (distance 2) so they never sit on the chain.

#define TT 16
#define CHUNK 128
#define MAXCHUNK 8192

__device__ float g_bufA[MAXCHUNK + 1];
__device__ float g_bufB[MAXCHUNK + 1];

struct SP {
  float A1, B1, oo1;    // sigmoid path: exp(-z1) = ex2(A1*c + B1)
  float A2, B2;         // tanh path:    exp(2*z2) = ex2(A2*c + B2)
  float sv, m2sv;       // ov1 = sv*tanh = fma(m2sv, rcp(1+e2), sv)
  float E;              // eb * 500
};

__device__ __forceinline__ float ex2f(float x) {
  float y; asm("ex2.approx.f32 %0, %1;" : "=f"(y) : "f"(x)); return y;
}
__device__ __forceinline__ float rcpf(float x) {
  float y; asm("rcp.approx.f32 %0, %1;" : "=f"(y) : "f"(x)); return y;
}

__device__ __forceinline__ SP make_params(
    const float* cm, const float* cs,
    const float* wr_om, const float* wr_fm, const float* wr_vm,
    const float* b0_om, const float* wb1_om, const float* ws_vm, const float* b0_rm) {
  const float L2E = 1.4426950408889634f;
  float mo = cm[0], so = cs[0];
  float e_om = expf(wr_om[0]);
  float e_fm = expf(wr_fm[0]);
  float oo1 = e_om / (e_om + e_fm);
  float wb1 = wb1_om[0], b0 = b0_om[0];
  float eb = expf(b0_rm[0]);
  float ws = expf(ws_vm[0]);
  float sv = 1.0f / (1.0f + expf(-wr_vm[0]));
  float k1 = wb1 / so;
  SP p;
  p.A1 = -L2E * k1;
  p.B1 = -L2E * (b0 - mo * k1);
  p.oo1 = oo1;
  p.A2 = 2.0f * L2E * ws * (1.0f / 500.0f);
  p.B2 = -2.0f * L2E * eb * ws;
  p.sv = sv;
  p.m2sv = -2.0f * sv;
  p.E = 500.0f * eb;
  return p;
}

__device__ __forceinline__ float step_c(float c, float u, const SP& P) {
  float e1 = ex2f(fmaf(c, P.A1, P.B1));
  float r1 = rcpf(1.0f + e1);
  float f  = fmaf(-P.oo1, r1, 1.0f);
  float e2 = ex2f(fmaf(c, P.A2, P.B2));
  float r2 = rcpf(1.0f + e2);
  float ov1 = fmaf(P.m2sv, r2, P.sv);
  float ov = fminf(ov1, f);
  float a  = fabsf(c - P.E);
  float fcu = fmaf(f, c, u);
  return fmaf(-ov, a, fcu);
}

// Run one chunk with prefetched float4 loads; returns end state.
__device__ __forceinline__ float run_chunk(float c, const float* xp, int m, const SP& P) {
  const float4* xv = (const float4*)xp;
  int groups = m >> 2;                       // m is a multiple of 16
  float4 b0 = xv[0];
  float4 b1 = (groups > 1) ? xv[1] : make_float4(0.f, 0.f, 0.f, 0.f);
  #pragma unroll 4
  for (int j = 0; j < groups; j++) {
    float4 nn = (j + 2 < groups) ? xv[j + 2] : make_float4(0.f, 0.f, 0.f, 0.f);
    c = step_c(c, b0.x, P);
    c = step_c(c, b0.y, P);
    c = step_c(c, b0.z, P);
    c = step_c(c, b0.w, P);
    b0 = b1; b1 = nn;
  }
  return c;
}

// relaxation sweep. mode: 0 = first sweep (start from Ini_C guess, write B),
//                         1 = read B write A,  2 = read A write B
__global__ void sweep_kernel(
    const float* __restrict__ x,
    const float* cm, const float* cs,
    const float* wr_om, const float* wr_fm, const float* wr_vm,
    const float* b0_om, const float* wb1_om, const float* ws_vm, const float* b0_rm,
    const float* IniC, const int* tlp, int BT, int mode) {
  int p = blockIdx.x * blockDim.x + threadIdx.x;
  int tl = tlp[0];
  int nsteps = BT - tl * TT;
  if (nsteps <= 0) return;
  int nchunk = (nsteps + CHUNK - 1) / CHUNK;
  float* s_out = (mode == 1) ? g_bufA : g_bufB;
  if (p == 0) s_out[0] = IniC[0];
  if (p >= nchunk || p >= MAXCHUNK) return;
  float c;
  if (mode == 0)      c = IniC[0];
  else if (mode == 1) c = g_bufB[p];
  else                c = g_bufA[p];
  SP P = make_params(cm, cs, wr_om, wr_fm, wr_vm, b0_om, wb1_om, ws_vm, b0_rm);
  const float* xp = x + tl * TT + p * CHUNK;
  int m = min(CHUNK, nsteps - p * CHUNK);
  c = run_chunk(c, xp, m, P);
  s_out[p + 1] = c;
}

// final pass: replay each chunk from converged start state (in g_bufB),
// emitting the 6 outputs at each row's last step; also zero time_lag rows.
__global__ void out_kernel(
    const float* __restrict__ x,
    const float* cm, const float* cs,
    const float* wr_om, const float* wr_fm, const float* wr_vm,
    const float* b0_om, const float* wb1_om, const float* ws_vm, const float* b0_rm,
    const int* tlp, int BT, int Bn, float* __restrict__ out) {
  int p = blockIdx.x * blockDim.x + threadIdx.x;
  int tl = tlp[0];
  int tot = gridDim.x * blockDim.x;
  // zero skipped rows (b < time_lag)
  for (int r = p; r < tl && r < Bn; r += tot) {
    #pragma unroll
    for (int j = 0; j < 6; j++) out[(long)j * Bn + r] = 0.0f;
  }
  int nsteps = BT - tl * TT;
  if (nsteps <= 0) return;
  int nchunk = (nsteps + CHUNK - 1) / CHUNK;
  if (p >= nchunk || p >= MAXCHUNK) return;
  SP P = make_params(cm, cs, wr_om, wr_fm, wr_vm, b0_om, wb1_om, ws_vm, b0_rm);
  float c = g_bufB[p];
  const float* xp = x + tl * TT + p * CHUNK;
  int m = min(CHUNK, nsteps - p * CHUNK);

  float* h_n  = out;
  float* c_n  = out + (long)Bn;
  float* oo_o = out + 2L * Bn;
  float* f_o  = out + 3L * Bn;
  float* ov_o = out + 4L * Bn;
  float* mr_o = out + 5L * Bn;

  const float4* xv = (const float4*)xp;
  int groups = m >> 2;
  float4 v0 = xv[0];
  float4 v1 = (groups > 1) ? xv[1] : make_float4(0.f, 0.f, 0.f, 0.f);
  for (int j = 0; j < groups; j++) {
    float4 nn = (j + 2 < groups) ? xv[j + 2] : make_float4(0.f, 0.f, 0.f, 0.f);
    float us[4] = {v0.x, v0.y, v0.z, v0.w};
    #pragma unroll
    for (int k = 0; k < 4; k++) {
      float u = us[k];
      float e1 = ex2f(fmaf(c, P.A1, P.B1));
      float r1 = rcpf(1.0f + e1);
      float f  = fmaf(-P.oo1, r1, 1.0f);
      float e2 = ex2f(fmaf(c, P.A2, P.B2));
      float r2 = rcpf(1.0f + e2);
      float ov1 = fmaf(P.m2sv, r2, P.sv);
      float ov = fminf(ov1, f);
      float a  = fabsf(c - P.E);
      float fcu = fmaf(f, c, u);
      int i = j * 4 + k;
      if ((i & (TT - 1)) == (TT - 1)) {
        int row = tl + ((p * CHUNK + i) >> 4);
        float oo = P.oo1 * r1;
        h_n[row]  = oo * c;
        c_n[row]  = c;
        oo_o[row] = oo;
        f_o[row]  = f;
        ov_o[row] = ov;
        mr_o[row] = -ov * a;
      }
      c = fmaf(-ov, a, fcu);
    }
    v0 = v1; v1 = nn;
  }
}

extern "C" void kernel_launch(void* const* d_in, const int* in_sizes, int n_in,
                              void* d_out, int out_size) {
  const float* x      = (const float*)d_in[0];
  const float* cm     = (const float*)d_in[2];
  const float* cs     = (const float*)d_in[3];
  const float* IniC   = (const float*)d_in[4];
  const float* wr_om  = (const float*)d_in[5];
  const float* wr_fm  = (const float*)d_in[6];
  const float* wr_vm  = (const float*)d_in[7];
  const float* b0_om  = (const float*)d_in[8];
  const float* wb1_om = (const float*)d_in[9];
  const float* ws_vm  = (const float*)d_in[10];
  const float* b0_rm  = (const float*)d_in[11];
  const int*   tlp    = (const int*)d_in[13];
  float* out = (float*)d_out;

  int BT = in_sizes[0];
  int Bn = out_size / 6;

  int nchunk_max = (BT + CHUNK - 1) / CHUNK;
  if (nchunk_max > MAXCHUNK) nchunk_max = MAXCHUNK;

  const int TPB = 128;
  int gb = (nchunk_max + TPB - 1) / TPB;

  // sweep1 (guess) -> B ; sweep2 B -> A ; sweep3 A -> B ; out reads B
  sweep_kernel<<<gb, TPB>>>(x, cm, cs, wr_om, wr_fm, wr_vm, b0_om, wb1_om, ws_vm, b0_rm, IniC, tlp, BT, 0);
  sweep_kernel<<<gb, TPB>>>(x, cm, cs, wr_om, wr_fm, wr_vm, b0_om, wb1_om, ws_vm, b0_rm, IniC, tlp, BT, 1);
  sweep_kernel<<<gb, TPB>>>(x, cm, cs, wr_om, wr_fm, wr_vm, b0_om, wb1_om, ws_vm, b0_rm, IniC, tlp, BT, 2);
  out_kernel<<<gb, TPB>>>(x, cm, cs, wr_om, wr_fm, wr_vm, b0_om, wb1_om, ws_vm, b0_rm, tlp, BT, Bn, out);
}

// round 5
// speedup vs baseline: 6.4167x; 1.6367x over previous
#include <cuda_runtime.h>

// Nonlinear scalar RNN scan, B*T = 1,048,576 sequential steps.
// Chunked fixed-point relaxation (contraction |J| <= ~0.87 worst case):
//   CHUNK=64 steps (4 rows of T=16), nchunk = 16384
//   3 sweeps (guess -> B -> A -> B) + out pass   (4 launches)
// Hot loops are fully unrolled with compile-time trip counts: no runtime
// branches, float4 loads prefetched 2 groups ahead of the dependent chain.

#define TT 16
#define CHUNK 64
#define GROUPS (CHUNK / 4)
#define MAXCHUNK 16384

__device__ float g_bufA[MAXCHUNK + 1];
__device__ float g_bufB[MAXCHUNK + 1];

struct SP {
  float A1, B1, oo1;    // sigmoid path: exp(-z1) = ex2(A1*c + B1)
  float A2, B2;         // tanh path:    exp(2*z2) = ex2(A2*c + B2)
  float sv, m2sv;       // ov1 = sv*tanh = fma(m2sv, rcp(1+e2), sv)
  float E;              // eb * 500
};

__device__ __forceinline__ float ex2f(float x) {
  float y; asm("ex2.approx.f32 %0, %1;" : "=f"(y) : "f"(x)); return y;
}
__device__ __forceinline__ float rcpf(float x) {
  float y; asm("rcp.approx.f32 %0, %1;" : "=f"(y) : "f"(x)); return y;
}

__device__ __forceinline__ SP make_params(
    const float* cm, const float* cs,
    const float* wr_om, const float* wr_fm, const float* wr_vm,
    const float* b0_om, const float* wb1_om, const float* ws_vm, const float* b0_rm) {
  const float L2E = 1.4426950408889634f;
  float mo = cm[0], so = cs[0];
  float e_om = expf(wr_om[0]);
  float e_fm = expf(wr_fm[0]);
  float oo1 = e_om / (e_om + e_fm);
  float wb1 = wb1_om[0], b0 = b0_om[0];
  float eb = expf(b0_rm[0]);
  float ws = expf(ws_vm[0]);
  float sv = 1.0f / (1.0f + expf(-wr_vm[0]));
  float k1 = wb1 / so;
  SP p;
  p.A1 = -L2E * k1;
  p.B1 = -L2E * (b0 - mo * k1);
  p.oo1 = oo1;
  p.A2 = 2.0f * L2E * ws * (1.0f / 500.0f);
  p.B2 = -2.0f * L2E * eb * ws;
  p.sv = sv;
  p.m2sv = -2.0f * sv;
  p.E = 500.0f * eb;
  return p;
}

// One recurrence step. Critical chain ~52 cyc (two MUFU paths in parallel).
__device__ __forceinline__ float step_c(float c, float u, const SP& P) {
  float e1 = ex2f(fmaf(c, P.A1, P.B1));
  float r1 = rcpf(1.0f + e1);
  float f  = fmaf(-P.oo1, r1, 1.0f);
  float e2 = ex2f(fmaf(c, P.A2, P.B2));
  float r2 = rcpf(1.0f + e2);
  float ov1 = fmaf(P.m2sv, r2, P.sv);
  float ov = fminf(ov1, f);
  float a  = fabsf(c - P.E);
  float fcu = fmaf(f, c, u);
  return fmaf(-ov, a, fcu);
}

// Full chunk: compile-time trip count, branch-free prefetch (distance 2).
__device__ __forceinline__ float run_chunk_full(float c, const float4* __restrict__ xv,
                                                const SP& P) {
  float4 b0 = xv[0];
  float4 b1 = xv[1];
  #pragma unroll
  for (int j = 0; j < GROUPS; j++) {
    float4 nn;
    if (j + 2 < GROUPS) nn = xv[j + 2];      // static condition: no runtime branch
    c = step_c(c, b0.x, P);
    c = step_c(c, b0.y, P);
    c = step_c(c, b0.z, P);
    c = step_c(c, b0.w, P);
    b0 = b1;
    if (j + 2 < GROUPS) b1 = nn;
  }
  return c;
}

// relaxation sweep. mode: 0 = guess(Ini_C) -> B,  1 = B -> A,  2 = A -> B
__global__ void sweep_kernel(
    const float* __restrict__ x,
    const float* cm, const float* cs,
    const float* wr_om, const float* wr_fm, const float* wr_vm,
    const float* b0_om, const float* wb1_om, const float* ws_vm, const float* b0_rm,
    const float* IniC, const int* tlp, int BT, int mode) {
  int p = blockIdx.x * blockDim.x + threadIdx.x;
  int tl = tlp[0];
  int nsteps = BT - tl * TT;
  if (nsteps <= 0) return;
  int nchunk = (nsteps + CHUNK - 1) / CHUNK;
  float* s_out = (mode == 1) ? g_bufA : g_bufB;
  if (p == 0) s_out[0] = IniC[0];
  if (p >= nchunk || p >= MAXCHUNK) return;
  float c;
  if (mode == 0)      c = IniC[0];
  else if (mode == 1) c = g_bufB[p];
  else                c = g_bufA[p];
  SP P = make_params(cm, cs, wr_om, wr_fm, wr_vm, b0_om, wb1_om, ws_vm, b0_rm);
  const float* xp = x + tl * TT + p * CHUNK;
  int m = min(CHUNK, nsteps - p * CHUNK);
  if (m == CHUNK) {
    c = run_chunk_full(c, (const float4*)xp, P);
  } else {
    for (int i = 0; i < m; i++) c = step_c(c, xp[i], P);   // tail chunk only
  }
  s_out[p + 1] = c;
}

// final pass: replay each chunk from converged start (g_bufB), 4 rows of 16
// steps each; emit the 6 outputs at each row's step 15. No per-step branches.
__global__ void out_kernel(
    const float* __restrict__ x,
    const float* cm, const float* cs,
    const float* wr_om, const float* wr_fm, const float* wr_vm,
    const float* b0_om, const float* wb1_om, const float* ws_vm, const float* b0_rm,
    const int* tlp, int BT, int Bn, float* __restrict__ out) {
  int p = blockIdx.x * blockDim.x + threadIdx.x;
  int tl = tlp[0];
  int tot = gridDim.x * blockDim.x;
  for (int r = p; r < tl && r < Bn; r += tot) {
    #pragma unroll
    for (int j = 0; j < 6; j++) out[(long)j * Bn + r] = 0.0f;
  }
  int nsteps = BT - tl * TT;
  if (nsteps <= 0) return;
  int nchunk = (nsteps + CHUNK - 1) / CHUNK;
  if (p >= nchunk || p >= MAXCHUNK) return;
  SP P = make_params(cm, cs, wr_om, wr_fm, wr_vm, b0_om, wb1_om, ws_vm, b0_rm);
  float c = g_bufB[p];
  const float* xp = x + tl * TT + p * CHUNK;
  int m = min(CHUNK, nsteps - p * CHUNK);

  float* h_n  = out;
  float* c_n  = out + (long)Bn;
  float* oo_o = out + 2L * Bn;
  float* f_o  = out + 3L * Bn;
  float* ov_o = out + 4L * Bn;
  float* mr_o = out + 5L * Bn;

  if (m == CHUNK) {
    const float4* xv = (const float4*)xp;
    float4 q0 = xv[0], q1 = xv[1], q2 = xv[2], q3 = xv[3];
    #pragma unroll
    for (int r = 0; r < 4; r++) {
      float4 n0, n1, n2, n3;
      if (r < 3) {                       // static: next row's loads issue early
        n0 = xv[4 * (r + 1)];
        n1 = xv[4 * (r + 1) + 1];
        n2 = xv[4 * (r + 1) + 2];
        n3 = xv[4 * (r + 1) + 3];
      }
      float u[16] = {q0.x, q0.y, q0.z, q0.w, q1.x, q1.y, q1.z, q1.w,
                     q2.x, q2.y, q2.z, q2.w, q3.x, q3.y, q3.z, q3.w};
      #pragma unroll
      for (int k = 0; k < 15; k++) c = step_c(c, u[k], P);
      // emitting step (k = 15)
      {
        float e1 = ex2f(fmaf(c, P.A1, P.B1));
        float r1 = rcpf(1.0f + e1);
        float f  = fmaf(-P.oo1, r1, 1.0f);
        float e2 = ex2f(fmaf(c, P.A2, P.B2));
        float r2 = rcpf(1.0f + e2);
        float ov1 = fmaf(P.m2sv, r2, P.sv);
        float ov = fminf(ov1, f);
        float a  = fabsf(c - P.E);
        float fcu = fmaf(f, c, u[15]);
        int row = tl + p * 4 + r;
        float oo = P.oo1 * r1;
        h_n[row]  = oo * c;
        c_n[row]  = c;
        oo_o[row] = oo;
        f_o[row]  = f;
        ov_o[row] = ov;
        mr_o[row] = -ov * a;
        c = fmaf(-ov, a, fcu);
      }
      if (r < 3) { q0 = n0; q1 = n1; q2 = n2; q3 = n3; }
    }
  } else {
    // tail chunk (m in {16,32,48}): simple per-step path
    for (int i = 0; i < m; i++) {
      float u = xp[i];
      float e1 = ex2f(fmaf(c, P.A1, P.B1));
      float r1 = rcpf(1.0f + e1);
      float f  = fmaf(-P.oo1, r1, 1.0f);
      float e2 = ex2f(fmaf(c, P.A2, P.B2));
      float r2 = rcpf(1.0f + e2);
      float ov1 = fmaf(P.m2sv, r2, P.sv);
      float ov = fminf(ov1, f);
      float a  = fabsf(c - P.E);
      float fcu = fmaf(f, c, u);
      if ((i & (TT - 1)) == (TT - 1)) {
        int row = tl + ((p * CHUNK + i) >> 4);
        float oo = P.oo1 * r1;
        h_n[row]  = oo * c;
        c_n[row]  = c;
        oo_o[row] = oo;
        f_o[row]  = f;
        ov_o[row] = ov;
        mr_o[row] = -ov * a;
      }
      c = fmaf(-ov, a, fcu);
    }
  }
}

extern "C" void kernel_launch(void* const* d_in, const int* in_sizes, int n_in,
                              void* d_out, int out_size) {
  const float* x      = (const float*)d_in[0];
  const float* cm     = (const float*)d_in[2];
  const float* cs     = (const float*)d_in[3];
  const float* IniC   = (const float*)d_in[4];
  const float* wr_om  = (const float*)d_in[5];
  const float* wr_fm  = (const float*)d_in[6];
  const float* wr_vm  = (const float*)d_in[7];
  const float* b0_om  = (const float*)d_in[8];
  const float* wb1_om = (const float*)d_in[9];
  const float* ws_vm  = (const float*)d_in[10];
  const float* b0_rm  = (const float*)d_in[11];
  const int*   tlp    = (const int*)d_in[13];
  float* out = (float*)d_out;

  int BT = in_sizes[0];
  int Bn = out_size / 6;

  int nchunk_max = (BT + CHUNK - 1) / CHUNK;
  if (nchunk_max > MAXCHUNK) nchunk_max = MAXCHUNK;

  const int TPB = 128;
  int gb = (nchunk_max + TPB - 1) / TPB;

  // sweep1 (guess) -> B ; sweep2 B -> A ; sweep3 A -> B ; out reads B
  sweep_kernel<<<gb, TPB>>>(x, cm, cs, wr_om, wr_fm, wr_vm, b0_om, wb1_om, ws_vm, b0_rm, IniC, tlp, BT, 0);
  sweep_kernel<<<gb, TPB>>>(x, cm, cs, wr_om, wr_fm, wr_vm, b0_om, wb1_om, ws_vm, b0_rm, IniC, tlp, BT, 1);
  sweep_kernel<<<gb, TPB>>>(x, cm, cs, wr_om, wr_fm, wr_vm, b0_om, wb1_om, ws_vm, b0_rm, IniC, tlp, BT, 2);
  out_kernel<<<gb, TPB>>>(x, cm, cs, wr_om, wr_fm, wr_vm, b0_om, wb1_om, ws_vm, b0_rm, tlp, BT, Bn, out);
}

// round 7
// speedup vs baseline: 8.8168x; 1.3740x over previous
#include <cuda_runtime.h>

// Nonlinear scalar RNN scan, B*T = 1,048,576 sequential steps.
// Single persistent fused kernel: 3 relaxation sweeps + output pass, separated
// by one-wave grid barriers (grid 256x128 = 32768 threads, all co-resident).
//   CHUNK=32 steps/thread (2 rows of T=16); x held in registers across passes.
// Contraction |J| <= ~0.87 worst case: 96 relax steps => boundary error < 5e-5
// absolute, far below the 1e-3 rel threshold (realistic J ~0.75 => ~1e-12).

#define TT 16
#define CHUNK 32
#define NTHREAD 128
#define NBLOCK 256
#define NTOT (NTHREAD * NBLOCK)       // 32768 threads == nchunk at full size
#define MAXCHUNK NTOT

__device__ float g_bufA[MAXCHUNK + 1];
__device__ float g_bufB[MAXCHUNK + 1];
__device__ unsigned g_cnt[3];
__device__ unsigned g_done;

struct SP {
  float A1, B1, oo1;    // sigmoid path: exp(-z1) = ex2(A1*c + B1)
  float A2, B2;         // tanh path:    exp(2*z2) = ex2(A2*c + B2)
  float sv, m2sv;       // ov1 = sv*tanh = fma(m2sv, rcp(1+e2), sv)
  float E;              // eb * 500
};

__device__ __forceinline__ float ex2f(float x) {
  float y; asm("ex2.approx.f32 %0, %1;" : "=f"(y) : "f"(x)); return y;
}
__device__ __forceinline__ float rcpf(float x) {
  float y; asm("rcp.approx.f32 %0, %1;" : "=f"(y) : "f"(x)); return y;
}

__device__ __forceinline__ SP make_params(
    const float* cm, const float* cs,
    const float* wr_om, const float* wr_fm, const float* wr_vm,
    const float* b0_om, const float* wb1_om, const float* ws_vm, const float* b0_rm) {
  const float L2E = 1.4426950408889634f;
  float mo = cm[0], so = cs[0];
  float e_om = expf(wr_om[0]);
  float e_fm = expf(wr_fm[0]);
  float oo1 = e_om / (e_om + e_fm);
  float wb1 = wb1_om[0], b0 = b0_om[0];
  float eb = expf(b0_rm[0]);
  float ws = expf(ws_vm[0]);
  float sv = 1.0f / (1.0f + expf(-wr_vm[0]));
  float k1 = wb1 / so;
  SP p;
  p.A1 = -L2E * k1;
  p.B1 = -L2E * (b0 - mo * k1);
  p.oo1 = oo1;
  p.A2 = 2.0f * L2E * ws * (1.0f / 500.0f);
  p.B2 = -2.0f * L2E * eb * ws;
  p.sv = sv;
  p.m2sv = -2.0f * sv;
  p.E = 500.0f * eb;
  return p;
}

// One recurrence step. Critical chain ~52 cyc (two MUFU paths in parallel).
__device__ __forceinline__ float step_c(float c, float u, const SP& P) {
  float e1 = ex2f(fmaf(c, P.A1, P.B1));
  float r1 = rcpf(1.0f + e1);
  float f  = fmaf(-P.oo1, r1, 1.0f);
  float e2 = ex2f(fmaf(c, P.A2, P.B2));
  float r2 = rcpf(1.0f + e2);
  float ov1 = fmaf(P.m2sv, r2, P.sv);
  float ov = fminf(ov1, f);
  float a  = fabsf(c - P.E);
  float fcu = fmaf(f, c, u);
  return fmaf(-ov, a, fcu);
}

// 32 steps from register-resident x. Fully unrolled, branch-free.
__device__ __forceinline__ float run32(float c, const float4* q, const SP& P) {
  #pragma unroll
  for (int j = 0; j < 8; j++) {
    c = step_c(c, q[j].x, P);
    c = step_c(c, q[j].y, P);
    c = step_c(c, q[j].z, P);
    c = step_c(c, q[j].w, P);
  }
  return c;
}

// One-wave grid barrier (all NBLOCK blocks co-resident by construction).
__device__ __forceinline__ void grid_bar(int i) {
  __threadfence();
  __syncthreads();
  if (threadIdx.x == 0) {
    atomicAdd(&g_cnt[i], 1u);
    while (*((volatile unsigned*)&g_cnt[i]) < gridDim.x) { __nanosleep(32); }
  }
  __syncthreads();
  __threadfence();
}

__global__ void __launch_bounds__(NTHREAD, 1)
fused_kernel(
    const float* __restrict__ x,
    const float* cm, const float* cs,
    const float* wr_om, const float* wr_fm, const float* wr_vm,
    const float* b0_om, const float* wb1_om, const float* ws_vm, const float* b0_rm,
    const float* IniC, const int* tlp, int BT, int Bn, float* __restrict__ out) {
  int p = blockIdx.x * NTHREAD + threadIdx.x;
  int tl = tlp[0];
  float ini = IniC[0];
  int nsteps = BT - tl * TT;
  if (nsteps < 0) nsteps = 0;
  int nchunk = (nsteps + CHUNK - 1) / CHUNK;
  if (nchunk > MAXCHUNK) nchunk = MAXCHUNK;

  bool active = (p < nchunk);
  const float* xbase = x + tl * TT + p * CHUNK;
  int m = active ? min(CHUNK, nsteps - p * CHUNK) : 0;
  bool full = active && (m == CHUNK);

  SP P = make_params(cm, cs, wr_om, wr_fm, wr_vm, b0_om, wb1_om, ws_vm, b0_rm);

  // x into registers (8 float4 = 32 floats), reused by all 4 passes.
  float4 q[8];
  if (full) {
    const float4* xv = (const float4*)xbase;
    #pragma unroll
    for (int j = 0; j < 8; j++) q[j] = xv[j];
  }

  // ---- sweep 1: guess Ini_C -> bufA ----
  if (p == 0) g_bufA[0] = ini;
  if (active) {
    float c = ini;
    if (full) c = run32(c, q, P);
    else      for (int i = 0; i < m; i++) c = step_c(c, xbase[i], P);
    g_bufA[p + 1] = c;
  }
  grid_bar(0);

  // ---- sweep 2: bufA -> bufB ----
  if (p == 0) g_bufB[0] = ini;
  if (active) {
    float c = g_bufA[p];
    if (full) c = run32(c, q, P);
    else      for (int i = 0; i < m; i++) c = step_c(c, xbase[i], P);
    g_bufB[p + 1] = c;
  }
  grid_bar(1);

  // ---- sweep 3: bufB -> bufA ----
  if (active) {
    float c = g_bufB[p];
    if (full) c = run32(c, q, P);
    else      for (int i = 0; i < m; i++) c = step_c(c, xbase[i], P);
    g_bufA[p + 1] = c;
  }
  if (p == 0) g_bufA[0] = ini;   // unchanged value; keep slot consistent
  grid_bar(2);

  // ---- output pass: replay from bufA, emit at each row's step 15 ----
  // zero skipped rows (b < time_lag)
  for (int r = p; r < tl && r < Bn; r += NTOT) {
    #pragma unroll
    for (int j = 0; j < 6; j++) out[(long)j * Bn + r] = 0.0f;
  }

  float* h_n  = out;
  float* c_n  = out + (long)Bn;
  float* oo_o = out + 2L * Bn;
  float* f_o  = out + 3L * Bn;
  float* ov_o = out + 4L * Bn;
  float* mr_o = out + 5L * Bn;

  if (active) {
    float c = g_bufA[p];
    if (full) {
      float u[32] = {q[0].x, q[0].y, q[0].z, q[0].w, q[1].x, q[1].y, q[1].z, q[1].w,
                     q[2].x, q[2].y, q[2].z, q[2].w, q[3].x, q[3].y, q[3].z, q[3].w,
                     q[4].x, q[4].y, q[4].z, q[4].w, q[5].x, q[5].y, q[5].z, q[5].w,
                     q[6].x, q[6].y, q[6].z, q[6].w, q[7].x, q[7].y, q[7].z, q[7].w};
      #pragma unroll
      for (int r = 0; r < 2; r++) {
        #pragma unroll
        for (int k = 0; k < 15; k++) c = step_c(c, u[r * 16 + k], P);
        // emitting step (k = 15)
        float e1 = ex2f(fmaf(c, P.A1, P.B1));
        float r1 = rcpf(1.0f + e1);
        float f  = fmaf(-P.oo1, r1, 1.0f);
        float e2 = ex2f(fmaf(c, P.A2, P.B2));
        float r2 = rcpf(1.0f + e2);
        float ov1 = fmaf(P.m2sv, r2, P.sv);
        float ov = fminf(ov1, f);
        float a  = fabsf(c - P.E);
        float fcu = fmaf(f, c, u[r * 16 + 15]);
        int row = tl + p * 2 + r;
        float oo = P.oo1 * r1;
        h_n[row]  = oo * c;
        c_n[row]  = c;
        oo_o[row] = oo;
        f_o[row]  = f;
        ov_o[row] = ov;
        mr_o[row] = -ov * a;
        c = fmaf(-ov, a, fcu);
      }
    } else {
      for (int i = 0; i < m; i++) {
        float u = xbase[i];
        float e1 = ex2f(fmaf(c, P.A1, P.B1));
        float r1 = rcpf(1.0f + e1);
        float f  = fmaf(-P.oo1, r1, 1.0f);
        float e2 = ex2f(fmaf(c, P.A2, P.B2));
        float r2 = rcpf(1.0f + e2);
        float ov1 = fmaf(P.m2sv, r2, P.sv);
        float ov = fminf(ov1, f);
        float a  = fabsf(c - P.E);
        float fcu = fmaf(f, c, u);
        if ((i & (TT - 1)) == (TT - 1)) {
          int row = tl + ((p * CHUNK + i) >> 4);
          float oo = P.oo1 * r1;
          h_n[row]  = oo * c;
          c_n[row]  = c;
          oo_o[row] = oo;
          f_o[row]  = f;
          ov_o[row] = ov;
          mr_o[row] = -ov * a;
        }
        c = fmaf(-ov, a, fcu);
      }
    }
  }

  // ---- reset barrier counters for next graph replay ----
  __syncthreads();
  if (threadIdx.x == 0) {
    unsigned d = atomicAdd(&g_done, 1u);
    if (d == gridDim.x - 1) {          // last block: everyone is past all barriers
      g_cnt[0] = 0; g_cnt[1] = 0; g_cnt[2] = 0;
      g_done = 0;
      __threadfence();
    }
  }
}

extern "C" void kernel_launch(void* const* d_in, const int* in_sizes, int n_in,
                              void* d_out, int out_size) {
  const float* x      = (const float*)d_in[0];
  const float* cm     = (const float*)d_in[2];
  const float* cs     = (const float*)d_in[3];
  const float* IniC   = (const float*)d_in[4];
  const float* wr_om  = (const float*)d_in[5];
  const float* wr_fm  = (const float*)d_in[6];
  const float* wr_vm  = (const float*)d_in[7];
  const float* b0_om  = (const float*)d_in[8];
  const float* wb1_om = (const float*)d_in[9];
  const float* ws_vm  = (const float*)d_in[10];
  const float* b0_rm  = (const float*)d_in[11];
  const int*   tlp    = (const int*)d_in[13];
  float* out = (float*)d_out;

  int BT = in_sizes[0];
  int Bn = out_size / 6;

  fused_kernel<<<NBLOCK, NTHREAD>>>(x, cm, cs, wr_om, wr_fm, wr_vm,
                                    b0_om, wb1_om, ws_vm, b0_rm,
                                    IniC, tlp, BT, Bn, out);
}

// round 8
// speedup vs baseline: 14.4737x; 1.6416x over previous
#include <cuda_runtime.h>

// Nonlinear scalar RNN scan, B*T = 1,048,576 sequential steps.
// Halo warm-in, zero synchronization: each thread owns a 32-step chunk
// (2 rows of T=16) and independently converges its start state by running
// WARM=80 extra steps from a guess (contraction J <~ 0.84 empirically:
// error at first emit has decayed 95 steps => ~1e-5 abs, below noise floor).
// One kernel, one pass, no barriers/atomics. Sequential depth = 112 steps.

#define TT 16
#define CHUNK 32
#define WARM 80
#define DEPTH (WARM + CHUNK)     // 112
#define NGROUP (DEPTH / 4)       // 28 float4 groups
#define NTHREAD 128

struct SP {
  float A1, B1, oo1;    // sigmoid path: exp(-z1) = ex2(A1*c + B1)
  float A2, B2;         // tanh path:    exp(2*z2) = ex2(A2*c + B2)
  float sv, m2sv;       // ov1 = sv*tanh = fma(m2sv, rcp(1+e2), sv)
  float E;              // eb * 500
};

__device__ __forceinline__ float ex2f(float x) {
  float y; asm("ex2.approx.f32 %0, %1;" : "=f"(y) : "f"(x)); return y;
}
__device__ __forceinline__ float rcpf(float x) {
  float y; asm("rcp.approx.f32 %0, %1;" : "=f"(y) : "f"(x)); return y;
}

__device__ __forceinline__ SP make_params(
    const float* cm, const float* cs,
    const float* wr_om, const float* wr_fm, const float* wr_vm,
    const float* b0_om, const float* wb1_om, const float* ws_vm, const float* b0_rm) {
  const float L2E = 1.4426950408889634f;
  float mo = cm[0], so = cs[0];
  float e_om = expf(wr_om[0]);
  float e_fm = expf(wr_fm[0]);
  float oo1 = e_om / (e_om + e_fm);
  float wb1 = wb1_om[0], b0 = b0_om[0];
  float eb = expf(b0_rm[0]);
  float ws = expf(ws_vm[0]);
  float sv = 1.0f / (1.0f + expf(-wr_vm[0]));
  float k1 = wb1 / so;
  SP p;
  p.A1 = -L2E * k1;
  p.B1 = -L2E * (b0 - mo * k1);
  p.oo1 = oo1;
  p.A2 = 2.0f * L2E * ws * (1.0f / 500.0f);
  p.B2 = -2.0f * L2E * eb * ws;
  p.sv = sv;
  p.m2sv = -2.0f * sv;
  p.E = 500.0f * eb;
  return p;
}

// One recurrence step. Critical chain ~57 cyc (two MUFU paths in parallel).
__device__ __forceinline__ float step_c(float c, float u, const SP& P) {
  float e1 = ex2f(fmaf(c, P.A1, P.B1));
  float r1 = rcpf(1.0f + e1);
  float f  = fmaf(-P.oo1, r1, 1.0f);
  float e2 = ex2f(fmaf(c, P.A2, P.B2));
  float r2 = rcpf(1.0f + e2);
  float ov1 = fmaf(P.m2sv, r2, P.sv);
  float ov = fminf(ov1, f);
  float a  = fabsf(c - P.E);
  float fcu = fmaf(f, c, u);
  return fmaf(-ov, a, fcu);
}

// Step that also emits the 6 outputs (used at each row's last timestep).
__device__ __forceinline__ float step_emit(float c, float u, const SP& P, int row,
                                           float* h_n, float* c_n, float* oo_o,
                                           float* f_o, float* ov_o, float* mr_o) {
  float e1 = ex2f(fmaf(c, P.A1, P.B1));
  float r1 = rcpf(1.0f + e1);
  float f  = fmaf(-P.oo1, r1, 1.0f);
  float e2 = ex2f(fmaf(c, P.A2, P.B2));
  float r2 = rcpf(1.0f + e2);
  float ov1 = fmaf(P.m2sv, r2, P.sv);
  float ov = fminf(ov1, f);
  float a  = fabsf(c - P.E);
  float fcu = fmaf(f, c, u);
  float oo = P.oo1 * r1;
  h_n[row]  = oo * c;        // oo * c_old
  c_n[row]  = c;             // c_old
  oo_o[row] = oo;
  f_o[row]  = f;
  ov_o[row] = ov;
  mr_o[row] = -ov * a;
  return fmaf(-ov, a, fcu);
}

__global__ void __launch_bounds__(NTHREAD)
halo_kernel(
    const float* __restrict__ x,
    const float* cm, const float* cs,
    const float* wr_om, const float* wr_fm, const float* wr_vm,
    const float* b0_om, const float* wb1_om, const float* ws_vm, const float* b0_rm,
    const float* IniC, const int* tlp, int BT, int Bn, float* __restrict__ out) {
  int p = blockIdx.x * NTHREAD + threadIdx.x;
  int tl = tlp[0];
  float ini = IniC[0];
  int nsteps = BT - tl * TT;
  if (nsteps < 0) nsteps = 0;
  int nchunk = (nsteps + CHUNK - 1) / CHUNK;

  // zero skipped rows (b < time_lag)
  int ntot = gridDim.x * blockDim.x;
  for (int r = p; r < tl && r < Bn; r += ntot) {
    #pragma unroll
    for (int j = 0; j < 6; j++) out[(long)j * Bn + r] = 0.0f;
  }
  if (p >= nchunk) return;

  SP P = make_params(cm, cs, wr_om, wr_fm, wr_vm, b0_om, wb1_om, ws_vm, b0_rm);
  int s0 = p * CHUNK;
  int m = min(CHUNK, nsteps - s0);
  const float* xb = x + tl * TT;

  float* h_n  = out;
  float* c_n  = out + (long)Bn;
  float* oo_o = out + 2L * Bn;
  float* f_o  = out + 3L * Bn;
  float* ov_o = out + 4L * Bn;
  float* mr_o = out + 5L * Bn;

  // Fast path: full chunk, and the 112-float read window fits the sequence.
  bool fast = (m == CHUNK) && (s0 >= WARM || nsteps >= DEPTH);
  if (fast) {
    int start = s0 - WARM;                 // multiple of 16; may be negative
    int goff = start >> 2;                 // float4 group offset (exact)
    int i0 = (start < 0) ? -start : -1;    // local step where global step 0 sits
    const float4* xv = (const float4*)xb;
    float c = ini;
    float4 b0 = xv[max(goff, 0)];
    float4 b1 = xv[max(1 + goff, 0)];
    #pragma unroll
    for (int g = 0; g < NGROUP; g++) {
      float4 nn;
      if (g + 2 < NGROUP) nn = xv[max(g + 2 + goff, 0)];
      float u4[4] = {b0.x, b0.y, b0.z, b0.w};
      #pragma unroll
      for (int k = 0; k < 4; k++) {
        const int i = 4 * g + k;
        // exact-restart points for threads whose window precedes step 0
        if (i == 16 || i == 48 || i == 80) c = (i == i0) ? ini : c;
        if (i == WARM + 15) {
          c = step_emit(c, u4[k], P, tl + 2 * p, h_n, c_n, oo_o, f_o, ov_o, mr_o);
        } else if (i == WARM + 31) {
          c = step_emit(c, u4[k], P, tl + 2 * p + 1, h_n, c_n, oo_o, f_o, ov_o, mr_o);
        } else {
          c = step_c(c, u4[k], P);
        }
      }
      b0 = b1;
      if (g + 2 < NGROUP) b1 = nn;
    }
  } else {
    // Generic path (tail chunks / tiny sequences): exact or warmed scalar run.
    int start = s0 - WARM;
    if (start < 0) start = 0;
    float c = ini;
    for (int i = start; i < s0 + m; i++) {
      float u = xb[i];
      if (i >= s0 && (i & (TT - 1)) == (TT - 1)) {
        c = step_emit(c, u, P, tl + (i >> 4), h_n, c_n, oo_o, f_o, ov_o, mr_o);
      } else {
        c = step_c(c, u, P);
      }
    }
  }
}

extern "C" void kernel_launch(void* const* d_in, const int* in_sizes, int n_in,
                              void* d_out, int out_size) {
  const float* x      = (const float*)d_in[0];
  const float* cm     = (const float*)d_in[2];
  const float* cs     = (const float*)d_in[3];
  const float* IniC   = (const float*)d_in[4];
  const float* wr_om  = (const float*)d_in[5];
  const float* wr_fm  = (const float*)d_in[6];
  const float* wr_vm  = (const float*)d_in[7];
  const float* b0_om  = (const float*)d_in[8];
  const float* wb1_om = (const float*)d_in[9];
  const float* ws_vm  = (const float*)d_in[10];
  const float* b0_rm  = (const float*)d_in[11];
  const int*   tlp    = (const int*)d_in[13];
  float* out = (float*)d_out;

  int BT = in_sizes[0];
  int Bn = out_size / 6;

  int nchunk = (BT + CHUNK - 1) / CHUNK;     // upper bound (tl only shrinks it)
  int gb = (nchunk + NTHREAD - 1) / NTHREAD;
  if (gb < 1) gb = 1;

  halo_kernel<<<gb, NTHREAD>>>(x, cm, cs, wr_om, wr_fm, wr_vm,
                               b0_om, wb1_om, ws_vm, b0_rm,
                               IniC, tlp, BT, Bn, out);
}